// round 15
// baseline (speedup 1.0000x reference)
#include <cuda_runtime.h>

#define IMG 512
#define TW 32
#define TH 32
#define IW2 44                    // staged row width (22 aligned pairs)
#define NP 22                     // pairs per staged row
#define IH 42
#define HROW 34
#define PL (IH * HROW)            // 1428 floats per hh plane
#define NPIX (16LL * 3 * 512 * 512)
#define GRID_X 16
#define GRID_Y 16
#define GRID_Z 48
#define GRID_TOTAL (GRID_X * GRID_Y * GRID_Z)

typedef unsigned long long u64;

__device__ double g_sum;
__device__ unsigned int g_count;

// Gaussian(sigma=1.5, K=11) weights, normalized — compile-time constants.
#define WV0 0.00102838f
#define WV1 0.00759876f
#define WV2 0.03600077f
#define WV3 0.10936069f
#define WV4 0.21300553f
#define WV5 0.26601172f

__device__ __forceinline__ u64 pack2(float lo, float hi) {
    u64 r; asm("mov.b64 %0,{%1,%2};" : "=l"(r) : "f"(lo), "f"(hi)); return r;
}
__device__ __forceinline__ void unpack2(u64 v, float& lo, float& hi) {
    asm("mov.b64 {%0,%1},%2;" : "=f"(lo), "=f"(hi) : "l"(v));
}
__device__ __forceinline__ u64 fma2(u64 a, u64 b, u64 c) {
    u64 d; asm("fma.rn.f32x2 %0,%1,%2,%3;" : "=l"(d) : "l"(a), "l"(b), "l"(c)); return d;
}
__device__ __forceinline__ u64 mul2(u64 a, u64 b) {
    u64 d; asm("mul.rn.f32x2 %0,%1,%2;" : "=l"(d) : "l"(a), "l"(b)); return d;
}
__device__ __forceinline__ u64 add2(u64 a, u64 b) {
    u64 d; asm("add.rn.f32x2 %0,%1,%2;" : "=l"(d) : "l"(a), "l"(b)); return d;
}
__device__ __forceinline__ u64 sub2(u64 a, u64 b) {
    u64 d; asm("sub.rn.f32x2 %0,%1,%2;" : "=l"(d) : "l"(a), "l"(b)); return d;
}

__global__ __launch_bounds__(256, 5) void ssim_kernel(
    const float* __restrict__ A, const float* __restrict__ B,
    float* __restrict__ out)
{
    // Staged rows span global cols [tx0-6, tx0+37]: 22 aligned pairs.
    __shared__ __align__(16) float sA[IH][IW2];
    __shared__ __align__(16) float sB[IH][IW2];
    __shared__ __align__(16) float hh[4][IH][HROW];   // A, B, A^2+B^2, AB
    __shared__ float wsum[8];

    const int tid = threadIdx.x;
    const int plane = blockIdx.z;
    const int tx0 = blockIdx.x * TW;
    const int ty0 = blockIdx.y * TH;
    const float* a = A + (size_t)plane * IMG * IMG;
    const float* b = B + (size_t)plane * IMG * IMG;

    // ---- Stage 42 rows x 22 aligned pairs, zero-padded. All LDG.64s issued
    //      before any STS (MLP=8); whole-pair bounds (no straddle: edges even).
    {
        float2 va[4], vb[4];
        int r = tid / NP;
        int c = tid - r * NP;                 // 256 = 11*22 + 14
        int rj[4], cj[4];
#pragma unroll
        for (int j = 0; j < 4; j++) {
            rj[j] = r; cj[j] = c;
            c += 14; if (c >= NP) { c -= NP; r += 1; }
            r += 11;
        }
#pragma unroll
        for (int j = 0; j < 4; j++) {
            int gy = ty0 - 5 + rj[j];
            int gx0 = tx0 - 6 + 2 * cj[j];
            bool ok = (rj[j] < IH) &&
                      (gy >= 0) && (gy < IMG) && (gx0 >= 0) && (gx0 < IMG);
            va[j] = make_float2(0.f, 0.f);
            vb[j] = make_float2(0.f, 0.f);
            if (ok) {
                int o = gy * IMG + gx0;
                va[j] = __ldg((const float2*)(a + o));
                vb[j] = __ldg((const float2*)(b + o));
            }
        }
#pragma unroll
        for (int j = 0; j < 4; j++) {
            if (rj[j] < IH) {
                *(float2*)&sA[rj[j]][2 * cj[j]] = va[j];
                *(float2*)&sB[rj[j]][2 * cj[j]] = vb[j];
            }
        }
    }
    __syncthreads();

    // Packed (duplicated) weights.
    const u64 W0p = pack2(WV0, WV0), W1p = pack2(WV1, WV1), W2p = pack2(WV2, WV2);
    const u64 W3p = pack2(WV3, WV3), W4p = pack2(WV4, WV4), W5p = pack2(WV5, WV5);

    auto wp = [&](int t) -> u64 {
        switch (t) {
            case 0: case 10: return W0p;
            case 1: case 9:  return W1p;
            case 2: case 8:  return W2p;
            case 3: case 7:  return W3p;
            case 4: case 6:  return W4p;
            default:         return W5p;
        }
    };

    // Parity-swapped even/odd 11-tap conv over 8 aligned pairs q[0..7]:
    //   X[s] = image[tx0-6+s]; out(c) = sum_k w[k] X[c+1+k], c = c0..c0+3.
    //   out(c0)=E0.hi+Q0.lo, out(c0+1)=E1.lo+Q0.hi,
    //   out(c0+2)=E1.hi+Q1.lo, out(c0+3)=E2.lo+Q1.hi.
    auto hplane = [&](const u64* q, float* dst) {
        u64 E0 = fma2(W0p, add2(q[0], q[5]),
                 fma2(W2p, add2(q[1], q[4]),
                 mul2(W4p, add2(q[2], q[3]))));
        u64 E1 = fma2(W0p, add2(q[1], q[6]),
                 fma2(W2p, add2(q[2], q[5]),
                 mul2(W4p, add2(q[3], q[4]))));
        u64 E2 = fma2(W0p, add2(q[2], q[7]),
                 fma2(W2p, add2(q[3], q[6]),
                 mul2(W4p, add2(q[4], q[5]))));
        u64 Q0 = fma2(W1p, add2(q[1], q[5]),
                 fma2(W3p, add2(q[2], q[4]), mul2(W5p, q[3])));
        u64 Q1 = fma2(W1p, add2(q[2], q[6]),
                 fma2(W3p, add2(q[3], q[5]), mul2(W5p, q[4])));
        float e0l, e0h, e1l, e1h, e2l, e2h;
        unpack2(E0, e0l, e0h);
        unpack2(E1, e1l, e1h);
        unpack2(E2, e2l, e2h);
        *(u64*)(dst)     = add2(pack2(e0h, e1l), Q0);
        *(u64*)(dst + 2) = add2(pack2(e1h, e2l), Q1);
    };

    // ---- Horizontal pass: 42 rows x 8 groups of 4 outputs (336 items).
    //      Single q[] buffer (re-read for products) keeps regs <= 51. ----
    auto hgroup = [&](int g) {
        int r = g >> 3;
        int c0 = (g & 7) << 2;
        const float* rowA = &sA[r][c0];
        const float* rowB = &sB[r][c0];
        float* dst = &hh[0][r][c0];
        u64 q[8];
#pragma unroll
        for (int j = 0; j < 8; j++) q[j] = *(const u64*)(rowA + 2 * j);
        hplane(q, dst);                                   // A
#pragma unroll
        for (int j = 0; j < 8; j++)
            q[j] = mul2(q[j], *(const u64*)(rowB + 2 * j));
        hplane(q, dst + 3 * PL);                          // AB
#pragma unroll
        for (int j = 0; j < 8; j++) q[j] = *(const u64*)(rowB + 2 * j);
        hplane(q, dst + PL);                              // B
#pragma unroll
        for (int j = 0; j < 8; j++) {
            u64 xa = *(const u64*)(rowA + 2 * j);
            q[j] = fma2(q[j], q[j], mul2(xa, xa));
        }
        hplane(q, dst + 2 * PL);                          // A^2 + B^2
    };
    hgroup(tid);
    if (tid >= 176) hgroup(tid + 80);   // overflow on warps 5-7 (not v-warps)
    __syncthreads();

    // ---- Vertical pass: 128 threads, each 2 cols x 4 rows, TWO sweeps of
    //      2 planes each (same total LDS as one sweep; half the live regs). ----
    const float C1 = 0.0001f;
    const float C2 = 0.0009f;
    float accf = 0.f;
    if (tid < 128) {
        int xp = tid & 15;        // column pair 0..15
        int rg = tid >> 4;        // row group 0..7 (4 rows each)
        const float* hp = &hh[0][rg * 4][2 * xp];

        u64 zero = pack2(0.f, 0.f);
        u64 m1[4], m2[4];
#pragma unroll
        for (int i = 0; i < 4; i++) { m1[i] = m2[i] = zero; }
#pragma unroll
        for (int k = 0; k < 14; k++) {
            u64 L0 = *(const u64*)(hp + k * HROW);
            u64 L1 = *(const u64*)(hp + k * HROW + PL);
#pragma unroll
            for (int i = 0; i < 4; i++) {
                int t = k - i;
                if (t >= 0 && t <= 10) {
                    u64 w = wp(t);
                    m1[i] = fma2(w, L0, m1[i]);
                    m2[i] = fma2(w, L1, m2[i]);
                }
            }
        }
        u64 ss[4], e12[4];
#pragma unroll
        for (int i = 0; i < 4; i++) { ss[i] = e12[i] = zero; }
#pragma unroll
        for (int k = 0; k < 14; k++) {
            u64 L2 = *(const u64*)(hp + k * HROW + 2 * PL);
            u64 L3 = *(const u64*)(hp + k * HROW + 3 * PL);
#pragma unroll
            for (int i = 0; i < 4; i++) {
                int t = k - i;
                if (t >= 0 && t <= 10) {
                    u64 w = wp(t);
                    ss[i]  = fma2(w, L2, ss[i]);
                    e12[i] = fma2(w, L3, e12[i]);
                }
            }
        }

        const u64 c1p = pack2(C1, C1);
        const u64 c2p = pack2(C2, C2);
#pragma unroll
        for (int i = 0; i < 4; i++) {
            u64 m1s = mul2(m1[i], m1[i]);
            u64 m2s = mul2(m2[i], m2[i]);
            u64 m12 = mul2(m1[i], m2[i]);
            u64 mss = add2(m1s, m2s);
            u64 p2  = add2(m12, m12);
            u64 t2  = add2(e12[i], e12[i]);
            u64 n1  = add2(p2, c1p);
            u64 n2  = add2(sub2(t2, p2), c2p);
            u64 d1  = add2(mss, c1p);
            u64 d2  = add2(sub2(ss[i], mss), c2p);
            u64 num = mul2(n1, n2);
            u64 den = mul2(d1, d2);
            float nx, ny, dx, dy;
            unpack2(num, nx, ny);
            unpack2(den, dx, dy);
            accf += __fdividef(nx, dx) + __fdividef(ny, dy);
        }
    }

    // ---- Block reduction + single-pass finalize ----
#pragma unroll
    for (int off = 16; off > 0; off >>= 1)
        accf += __shfl_down_sync(0xffffffffu, accf, off);
    if ((tid & 31) == 0) wsum[tid >> 5] = accf;
    __syncthreads();
    if (tid == 0) {
        float bsum = 0.f;
#pragma unroll
        for (int i = 0; i < 8; i++) bsum += wsum[i];
        atomicAdd(&g_sum, (double)bsum);
        __threadfence();
        unsigned int cold = atomicAdd(&g_count, 1u);
        if (cold == GRID_TOTAL - 1) {
            __threadfence();
            double s = *((volatile double*)&g_sum);
            out[0] = (float)(s / (double)NPIX);
            g_sum = 0.0;
            g_count = 0u;
            __threadfence();
        }
    }
}

extern "C" void kernel_launch(void* const* d_in, const int* in_sizes, int n_in,
                              void* d_out, int out_size)
{
    const float* A = (const float*)d_in[0];
    const float* B = (const float*)d_in[1];
    float* out = (float*)d_out;
    dim3 grid(GRID_X, GRID_Y, GRID_Z);
    ssim_kernel<<<grid, 256>>>(A, B, out);
}

// round 16
// speedup vs baseline: 1.0007x; 1.0007x over previous
#include <cuda_runtime.h>

#define IMG 512
#define TW 32
#define TH 32
#define IW 42
#define IH 42
#define HROW 34
#define PL (IH * HROW)            // 1428 floats per hh plane
#define NPIX (16LL * 3 * 512 * 512)
#define GRID_X 16
#define GRID_Y 16
#define GRID_Z 48
#define GRID_TOTAL (GRID_X * GRID_Y * GRID_Z)

typedef unsigned long long u64;

__device__ double g_sum;
__device__ unsigned int g_count;

// Gaussian(sigma=1.5, K=11) weights, normalized — compile-time constants.
#define WV0 0.00102838f
#define WV1 0.00759876f
#define WV2 0.03600077f
#define WV3 0.10936069f
#define WV4 0.21300553f
#define WV5 0.26601172f

__device__ __forceinline__ u64 pack2(float lo, float hi) {
    u64 r; asm("mov.b64 %0,{%1,%2};" : "=l"(r) : "f"(lo), "f"(hi)); return r;
}
__device__ __forceinline__ void unpack2(u64 v, float& lo, float& hi) {
    asm("mov.b64 {%0,%1},%2;" : "=f"(lo), "=f"(hi) : "l"(v));
}
__device__ __forceinline__ u64 fma2(u64 a, u64 b, u64 c) {
    u64 d; asm("fma.rn.f32x2 %0,%1,%2,%3;" : "=l"(d) : "l"(a), "l"(b), "l"(c)); return d;
}
__device__ __forceinline__ u64 mul2(u64 a, u64 b) {
    u64 d; asm("mul.rn.f32x2 %0,%1,%2;" : "=l"(d) : "l"(a), "l"(b)); return d;
}
__device__ __forceinline__ u64 add2(u64 a, u64 b) {
    u64 d; asm("add.rn.f32x2 %0,%1,%2;" : "=l"(d) : "l"(a), "l"(b)); return d;
}
__device__ __forceinline__ u64 sub2(u64 a, u64 b) {
    u64 d; asm("sub.rn.f32x2 %0,%1,%2;" : "=l"(d) : "l"(a), "l"(b)); return d;
}

__global__ __launch_bounds__(256, 5) void ssim_kernel(
    const float* __restrict__ A, const float* __restrict__ B,
    float* __restrict__ out)
{
    __shared__ __align__(16) float sA[IH][IW];
    __shared__ __align__(16) float sB[IH][IW];
    __shared__ __align__(16) float hh[4][IH][HROW];   // A, B, A^2+B^2, AB
    __shared__ float wsum[8];

    const int tid = threadIdx.x;
    const int plane = blockIdx.z;
    const int tx0 = blockIdx.x * TW;
    const int ty0 = blockIdx.y * TH;
    const float* a = A + (size_t)plane * IMG * IMG + (ty0 - 5) * IMG + (tx0 - 5);
    const float* b = B + (size_t)plane * IMG * IMG + (ty0 - 5) * IMG + (tx0 - 5);

    // ---- Stage haloed 42x42 tile, zero-padded. All LDGs issued before any
    //      STS (MLP=14). One division; incremental (r,c) thereafter. ----
    float* sAf = &sA[0][0];
    float* sBf = &sB[0][0];
    {
        float va[7], vb[7];
        int r = tid / IW;
        int c = tid - r * IW;                 // 256 = 6*42 + 4
        int rj[7], cj[7];
#pragma unroll
        for (int j = 0; j < 7; j++) {
            rj[j] = r; cj[j] = c;
            r += 6; c += 4;
            if (c >= IW) { c -= IW; r += 1; }
        }
#pragma unroll
        for (int j = 0; j < 7; j++) {
            int gy = ty0 - 5 + rj[j];
            int gx = tx0 - 5 + cj[j];
            bool ok = (rj[j] < IH) &&
                      (gy >= 0) && (gy < IMG) && (gx >= 0) && (gx < IMG);
            int o = rj[j] * IMG + cj[j];
            va[j] = 0.f; vb[j] = 0.f;
            if (ok) { va[j] = __ldg(a + o); vb[j] = __ldg(b + o); }
        }
#pragma unroll
        for (int j = 0; j < 7; j++) {
            if (rj[j] < IH) {
                int idx = rj[j] * IW + cj[j];
                sAf[idx] = va[j];
                sBf[idx] = vb[j];
            }
        }
    }
    __syncthreads();

    // Packed (duplicated) weights.
    const u64 W0p = pack2(WV0, WV0), W1p = pack2(WV1, WV1), W2p = pack2(WV2, WV2);
    const u64 W3p = pack2(WV3, WV3), W4p = pack2(WV4, WV4), W5p = pack2(WV5, WV5);

    auto wp = [&](int t) -> u64 {
        switch (t) {
            case 0: case 10: return W0p;
            case 1: case 9:  return W1p;
            case 2: case 8:  return W2p;
            case 3: case 7:  return W3p;
            case 4: case 6:  return W4p;
            default:         return W5p;
        }
    };

    // Even/odd aligned-pair 11-tap conv, 8 outputs from 9 pairs q[0..8]:
    //   out(2p)   = E_p.lo + O_p.hi
    //   out(2p+1) = E_p.hi + O_{p+1}.lo
    auto hplane8 = [&](const u64* q, float* dst) {
        u64 E0 = fma2(W0p, add2(q[0], q[5]),
                 fma2(W2p, add2(q[1], q[4]), mul2(W4p, add2(q[2], q[3]))));
        u64 E1 = fma2(W0p, add2(q[1], q[6]),
                 fma2(W2p, add2(q[2], q[5]), mul2(W4p, add2(q[3], q[4]))));
        u64 E2 = fma2(W0p, add2(q[2], q[7]),
                 fma2(W2p, add2(q[3], q[6]), mul2(W4p, add2(q[4], q[5]))));
        u64 E3 = fma2(W0p, add2(q[3], q[8]),
                 fma2(W2p, add2(q[4], q[7]), mul2(W4p, add2(q[5], q[6]))));
        u64 O0 = fma2(W1p, add2(q[0], q[4]),
                 fma2(W3p, add2(q[1], q[3]), mul2(W5p, q[2])));
        u64 O1 = fma2(W1p, add2(q[1], q[5]),
                 fma2(W3p, add2(q[2], q[4]), mul2(W5p, q[3])));
        u64 O2 = fma2(W1p, add2(q[2], q[6]),
                 fma2(W3p, add2(q[3], q[5]), mul2(W5p, q[4])));
        u64 O3 = fma2(W1p, add2(q[3], q[7]),
                 fma2(W3p, add2(q[4], q[6]), mul2(W5p, q[5])));
        u64 O4 = fma2(W1p, add2(q[4], q[8]),
                 fma2(W3p, add2(q[5], q[7]), mul2(W5p, q[6])));
        float o0l, o0h, o1l, o1h, o2l, o2h, o3l, o3h, o4l, o4h;
        unpack2(O0, o0l, o0h);
        unpack2(O1, o1l, o1h);
        unpack2(O2, o2l, o2h);
        unpack2(O3, o3l, o3h);
        unpack2(O4, o4l, o4h);
        *(u64*)(dst)     = add2(E0, pack2(o0h, o1l));
        *(u64*)(dst + 2) = add2(E1, pack2(o1h, o2l));
        *(u64*)(dst + 4) = add2(E2, pack2(o2h, o3l));
        *(u64*)(dst + 6) = add2(E3, pack2(o3h, o4l));
    };

    // ---- Horizontal pass: 42 rows x 4 groups of 8 outputs (168 items).
    //      Single q[] buffer; re-reads keep live regs low. ----
    if (tid < IH * 4) {
        int g = tid;
        int r = g >> 2;
        int c0 = (g & 3) << 3;
        const float* rowA = &sA[r][c0];
        const float* rowB = &sB[r][c0];
        float* dst = &hh[0][r][c0];
        u64 q[9];
#pragma unroll
        for (int j = 0; j < 9; j++) q[j] = *(const u64*)(rowA + 2 * j);
        hplane8(q, dst);                                  // A
#pragma unroll
        for (int j = 0; j < 9; j++)
            q[j] = mul2(q[j], *(const u64*)(rowB + 2 * j));
        hplane8(q, dst + 3 * PL);                         // AB
#pragma unroll
        for (int j = 0; j < 9; j++) q[j] = *(const u64*)(rowB + 2 * j);
        hplane8(q, dst + PL);                             // B
#pragma unroll
        for (int j = 0; j < 9; j++) {
            u64 xa = *(const u64*)(rowA + 2 * j);
            q[j] = fma2(q[j], q[j], mul2(xa, xa));
        }
        hplane8(q, dst + 2 * PL);                         // A^2 + B^2
    }
    __syncthreads();

    // ---- Vertical pass: 128 threads, each 2 cols x 4 rows, TWO sweeps of
    //      2 planes each (same total LDS as one sweep; half the live regs). ----
    const float C1 = 0.0001f;
    const float C2 = 0.0009f;
    float accf = 0.f;
    if (tid < 128) {
        int xp = tid & 15;        // column pair 0..15
        int rg = tid >> 4;        // row group 0..7 (4 rows each)
        const float* hp = &hh[0][rg * 4][2 * xp];

        u64 zero = pack2(0.f, 0.f);
        u64 m1[4], m2[4];
#pragma unroll
        for (int i = 0; i < 4; i++) { m1[i] = m2[i] = zero; }
#pragma unroll
        for (int k = 0; k < 14; k++) {
            u64 L0 = *(const u64*)(hp + k * HROW);
            u64 L1 = *(const u64*)(hp + k * HROW + PL);
#pragma unroll
            for (int i = 0; i < 4; i++) {
                int t = k - i;
                if (t >= 0 && t <= 10) {
                    u64 w = wp(t);
                    m1[i] = fma2(w, L0, m1[i]);
                    m2[i] = fma2(w, L1, m2[i]);
                }
            }
        }
        u64 ss[4], e12[4];
#pragma unroll
        for (int i = 0; i < 4; i++) { ss[i] = e12[i] = zero; }
#pragma unroll
        for (int k = 0; k < 14; k++) {
            u64 L2 = *(const u64*)(hp + k * HROW + 2 * PL);
            u64 L3 = *(const u64*)(hp + k * HROW + 3 * PL);
#pragma unroll
            for (int i = 0; i < 4; i++) {
                int t = k - i;
                if (t >= 0 && t <= 10) {
                    u64 w = wp(t);
                    ss[i]  = fma2(w, L2, ss[i]);
                    e12[i] = fma2(w, L3, e12[i]);
                }
            }
        }

        const u64 c1p = pack2(C1, C1);
        const u64 c2p = pack2(C2, C2);
#pragma unroll
        for (int i = 0; i < 4; i++) {
            u64 m1s = mul2(m1[i], m1[i]);
            u64 m2s = mul2(m2[i], m2[i]);
            u64 m12 = mul2(m1[i], m2[i]);
            u64 mss = add2(m1s, m2s);
            u64 p2  = add2(m12, m12);
            u64 t2  = add2(e12[i], e12[i]);
            u64 n1  = add2(p2, c1p);
            u64 n2  = add2(sub2(t2, p2), c2p);
            u64 d1  = add2(mss, c1p);
            u64 d2  = add2(sub2(ss[i], mss), c2p);
            u64 num = mul2(n1, n2);
            u64 den = mul2(d1, d2);
            float nx, ny, dx, dy;
            unpack2(num, nx, ny);
            unpack2(den, dx, dy);
            accf += __fdividef(nx, dx) + __fdividef(ny, dy);
        }
    }

    // ---- Block reduction + single-pass finalize ----
#pragma unroll
    for (int off = 16; off > 0; off >>= 1)
        accf += __shfl_down_sync(0xffffffffu, accf, off);
    if ((tid & 31) == 0) wsum[tid >> 5] = accf;
    __syncthreads();
    if (tid == 0) {
        float bsum = 0.f;
#pragma unroll
        for (int i = 0; i < 8; i++) bsum += wsum[i];
        atomicAdd(&g_sum, (double)bsum);
        __threadfence();
        unsigned int cold = atomicAdd(&g_count, 1u);
        if (cold == GRID_TOTAL - 1) {
            __threadfence();
            double s = *((volatile double*)&g_sum);
            out[0] = (float)(s / (double)NPIX);
            g_sum = 0.0;
            g_count = 0u;
            __threadfence();
        }
    }
}

extern "C" void kernel_launch(void* const* d_in, const int* in_sizes, int n_in,
                              void* d_out, int out_size)
{
    const float* A = (const float*)d_in[0];
    const float* B = (const float*)d_in[1];
    float* out = (float*)d_out;
    dim3 grid(GRID_X, GRID_Y, GRID_Z);
    ssim_kernel<<<grid, 256>>>(A, B, out);
}